// round 16
// baseline (speedup 1.0000x reference)
#include <cuda_runtime.h>
#include <cuda_bf16.h>
#include <cstdint>

#define TLEN 8192
#define MH   4096
#define NF   4097
#define NHID 64
#define NCIN 32
#define NCOUT 32
#define NB   8
#define NCOL (NCIN * NCOUT)
#define QPAD (65 * 128)

// ---------------- device global scratch (allocation-free) ----------------
__device__ float2 d_TW8[TLEN];                 // e^{-2*pi*i*k/8192}
__device__ float  d_H2T[NHID * TLEN];          // MLP hidden, transposed [j][t]
__device__ float2 d_Xf[(NB * NCIN) * NF];      // rfft(x) rows
__device__ float2 d_Ff[NCOL * NF];             // filter spectra [c][f]
__device__ float2 d_Gf[(NB * NCOUT) * NF];     // contracted spectrum rows
__device__ __nv_bfloat16 d_w3hi[NCOL * NHID];  // w3 transposed [c][j], hi part
__device__ __nv_bfloat16 d_w3lo[NCOL * NHID];  // lo part
__device__ __nv_bfloat16 d_Bhi[QPAD * NHID];   // Hf as reals, [q][j], hi  (q>8193 stays 0)
__device__ __nv_bfloat16 d_Blo[QPAD * NHID];   // lo

__device__ __forceinline__ float2 cmulf(float2 a, float2 b) {
    return make_float2(fmaf(a.x, b.x, -a.y * b.y), fmaf(a.x, b.y, a.y * b.x));
}
__device__ __forceinline__ float2 cadd(float2 a, float2 b) { return make_float2(a.x + b.x, a.y + b.y); }
__device__ __forceinline__ float2 csub(float2 a, float2 b) { return make_float2(a.x - b.x, a.y - b.y); }
__device__ __forceinline__ float2 mulnegi(float2 a) { return make_float2(a.y, -a.x); }

#define PADIDX(a) ((a) + ((a) >> 3))

// ---------------- twiddle init ----------------
__global__ void init_tw_kernel() {
    int k = blockIdx.x * blockDim.x + threadIdx.x;
    if (k < TLEN) {
        double a = -2.0 * 3.14159265358979323846 * (double)k / (double)TLEN;
        d_TW8[k] = make_float2((float)cos(a), (float)sin(a));
    }
}

// ---------------- 8-point DFT in registers ----------------
__device__ __forceinline__ void fft8(const float2 c[8], float2 d[8]) {
    const float S = 0.70710678118654752440f;
    float2 a0 = cadd(c[0], c[4]), a1 = cadd(c[1], c[5]);
    float2 a2 = cadd(c[2], c[6]), a3 = cadd(c[3], c[7]);
    float2 b0 = csub(c[0], c[4]);
    float2 t1 = csub(c[1], c[5]);
    float2 b1 = make_float2(S * (t1.x + t1.y), S * (t1.y - t1.x));
    float2 t2 = csub(c[2], c[6]);
    float2 b2 = mulnegi(t2);
    float2 t3 = csub(c[3], c[7]);
    float2 b3 = make_float2(S * (t3.y - t3.x), -S * (t3.x + t3.y));
    float2 p0 = cadd(a0, a2), q0 = csub(a0, a2);
    float2 p1 = cadd(a1, a3), q1 = mulnegi(csub(a1, a3));
    d[0] = cadd(p0, p1); d[4] = csub(p0, p1);
    d[2] = cadd(q0, q1); d[6] = csub(q0, q1);
    float2 r0 = cadd(b0, b2), s0 = csub(b0, b2);
    float2 r1 = cadd(b1, b3), s1 = mulnegi(csub(b1, b3));
    d[1] = cadd(r0, r1); d[5] = csub(r0, r1);
    d[3] = cadd(s0, s1); d[7] = csub(s0, s1);
}

template <int L, int M, int SP, int DP>
__device__ __forceinline__ void stage8(const float2* __restrict__ src,
                                       float2* __restrict__ dst, int tid) {
    int j = tid / M;
    int k = tid - j * M;
    float2 c[8], d[8];
#pragma unroll
    for (int i = 0; i < 8; i++) {
        int a = tid + i * 512;
        c[i] = src[SP ? PADIDX(a) : a];
    }
    fft8(c, d);
    if (L > 1) {
        int tstep = j * (1024 / L);
        float2 w = d_TW8[tstep];
        float2 wt = w;
        d[1] = cmulf(d[1], w);
#pragma unroll
        for (int t = 2; t < 8; t++) {
            wt = cmulf(wt, w);
            d[t] = cmulf(d[t], wt);
        }
    }
    int base = k + M * 8 * j;
#pragma unroll
    for (int t = 0; t < 8; t++) {
        int a = base + M * t;
        dst[DP ? PADIDX(a) : a] = d[t];
    }
}

__device__ void fft4096(const float2* __restrict__ src, float2* A, float2* Bp, int tid) {
    stage8<512, 1, 0, 1>(src, Bp, tid);
    __syncthreads();
    stage8<64, 8, 1, 0>(Bp, A, tid);
    __syncthreads();
    stage8<8, 64, 0, 1>(A, Bp, tid);
    __syncthreads();
    stage8<1, 512, 1, 0>(Bp, A, tid);
    __syncthreads();
}

__device__ void rfft_post(const float2* A, float2* out, int tid) {
    for (int k = tid; k <= MH / 2; k += 512) {
        float2 Zk = A[k];
        float2 Zm = A[(MH - k) & (MH - 1)];
        float2 E = make_float2(0.5f * (Zk.x + Zm.x), 0.5f * (Zk.y - Zm.y));
        float2 O = make_float2(0.5f * (Zk.y + Zm.y), 0.5f * (Zm.x - Zk.x));
        float2 WO = cmulf(d_TW8[k], O);
        out[k]      = make_float2(E.x + WO.x, E.y + WO.y);
        out[MH - k] = make_float2(E.x - WO.x, -(E.y - WO.y));
    }
}

#define FFT_SMEM ((4096 + 4608) * sizeof(float2))

// ---------------- MLP hidden ----------------
__global__ void mlp_kernel(const float* __restrict__ w1, const float* __restrict__ b1,
                           const float* __restrict__ w2, const float* __restrict__ b2) {
    __shared__ float w2s[NHID * NHID];
    __shared__ float w1s[NHID], b1s[NHID], b2s[NHID];
    int tid = threadIdx.x;
    for (int i = tid; i < NHID * NHID; i += blockDim.x) w2s[i] = w2[i];
    if (tid < NHID) { w1s[tid] = w1[tid]; b1s[tid] = b1[tid]; b2s[tid] = b2[tid]; }
    __syncthreads();
    int t = blockIdx.x * blockDim.x + tid;
    float pos = (float)t / 8191.0f;
    float h1[NHID];
#pragma unroll
    for (int k = 0; k < NHID; k++) {
        float v = fmaf(pos, w1s[k], b1s[k]);
        h1[k] = 0.5f * v * (1.0f + erff(v * 0.70710678118654752f));
    }
    for (int j = 0; j < NHID; j++) {
        float acc = b2s[j];
#pragma unroll
        for (int k = 0; k < NHID; k++) acc = fmaf(h1[k], w2s[k * NHID + j], acc);
        float g = 0.5f * acc * (1.0f + erff(acc * 0.70710678118654752f));
        d_H2T[j * TLEN + t] = g;
    }
}

// ---------------- rfft of x rows ----------------
__global__ __launch_bounds__(512) void rfft_x_kernel(const float* __restrict__ x) {
    extern __shared__ float2 sm[];
    int row = blockIdx.x;
    fft4096((const float2*)(x + (size_t)row * TLEN), sm, sm + 4096, threadIdx.x);
    rfft_post(sm, d_Xf + (size_t)row * NF, threadIdx.x);
}

// ---------------- rfft of hidden rows, fused with bf16 hi/lo B-split write ----------------
__device__ __forceinline__ void storeB(int q, int j, float x) {
    __nv_bfloat16 h = __float2bfloat16(x);
    int o = q * NHID + j;
    d_Bhi[o] = h;
    d_Blo[o] = __float2bfloat16(x - __bfloat162float(h));
}

__global__ __launch_bounds__(512) void rfft_h_kernel() {
    extern __shared__ float2 sm[];
    float2* A = sm;
    int tid = threadIdx.x;
    int j = blockIdx.x;  // hidden unit 0..63
    fft4096((const float2*)(d_H2T + (size_t)j * TLEN), A, sm + 4096, tid);
    for (int k = tid; k <= MH / 2; k += 512) {
        float2 Zk = A[k];
        float2 Zm = A[(MH - k) & (MH - 1)];
        float2 E = make_float2(0.5f * (Zk.x + Zm.x), 0.5f * (Zk.y - Zm.y));
        float2 O = make_float2(0.5f * (Zk.y + Zm.y), 0.5f * (Zm.x - Zk.x));
        float2 WO = cmulf(d_TW8[k], O);
        storeB(2 * k, j, E.x + WO.x);
        storeB(2 * k + 1, j, E.y + WO.y);
        storeB(2 * (MH - k), j, E.x - WO.x);
        storeB(2 * (MH - k) + 1, j, -(E.y - WO.y));
    }
}

// ---------------- prep: w3 -> [c][j] bf16 hi/lo ----------------
__global__ void prep_w3_kernel(const float* __restrict__ w3) {
    int idx = blockIdx.x * 256 + threadIdx.x;  // 65536
    int j = idx >> 10, c = idx & 1023;
    float x = w3[idx];
    __nv_bfloat16 h = __float2bfloat16(x);
    int o = c * 64 + j;
    d_w3hi[o] = h;
    d_w3lo[o] = __float2bfloat16(x - __bfloat162float(h));
}

// ---------------- HMMA frequency GEMM (mma.sync, baseline PTX) ----------------
#define ASTR 72

__device__ __forceinline__ void mma16816(float c[4], const uint32_t a[4],
                                         uint32_t b0, uint32_t b1) {
    asm volatile(
        "mma.sync.aligned.m16n8k16.row.col.f32.bf16.bf16.f32 "
        "{%0,%1,%2,%3}, {%4,%5,%6,%7}, {%8,%9}, {%0,%1,%2,%3};"
        : "+f"(c[0]), "+f"(c[1]), "+f"(c[2]), "+f"(c[3])
        : "r"(a[0]), "r"(a[1]), "r"(a[2]), "r"(a[3]), "r"(b0), "r"(b1));
}

__global__ __launch_bounds__(256) void gemm_mma_kernel(const float* __restrict__ b3) {
    extern __shared__ __nv_bfloat16 ms[];
    __nv_bfloat16* Ah = ms;                    // [128][ASTR]
    __nv_bfloat16* Al = Ah + 128 * ASTR;
    __nv_bfloat16* Bh = Al + 128 * ASTR;
    __nv_bfloat16* Bl = Bh + 128 * ASTR;
    int tid = threadIdx.x;
    int q0 = blockIdx.x * 128;
    int c0 = blockIdx.y * 128;

    const uint4* w3h4 = (const uint4*)d_w3hi;
    const uint4* w3l4 = (const uint4*)d_w3lo;
    const uint4* bh4  = (const uint4*)d_Bhi;
    const uint4* bl4  = (const uint4*)d_Blo;
#pragma unroll
    for (int it = 0; it < 4; it++) {
        int idx = it * 256 + tid;
        int r = idx >> 3, u = idx & 7;
        *(uint4*)(Ah + r * ASTR + u * 8) = w3h4[(c0 + r) * 8 + u];
        *(uint4*)(Al + r * ASTR + u * 8) = w3l4[(c0 + r) * 8 + u];
        *(uint4*)(Bh + r * ASTR + u * 8) = bh4[(q0 + r) * 8 + u];
        *(uint4*)(Bl + r * ASTR + u * 8) = bl4[(q0 + r) * 8 + u];
    }
    __syncthreads();

    int wid = tid >> 5, l = tid & 31;
    int wm = (wid & 3) * 32;
    int wn = (wid >> 2) * 64;
    int lr = l >> 2;
    int lc = (l & 3) * 2;

    float acc[2][8][4];
#pragma unroll
    for (int mi = 0; mi < 2; mi++)
#pragma unroll
        for (int ni = 0; ni < 8; ni++)
#pragma unroll
            for (int r = 0; r < 4; r++) acc[mi][ni][r] = 0.f;

    const __nv_bfloat16* Aterm[3] = {Ah, Ah, Al};
    const __nv_bfloat16* Bterm[3] = {Bh, Bl, Bh};
#pragma unroll
    for (int t = 0; t < 3; t++) {
        const __nv_bfloat16* A = Aterm[t];
        const __nv_bfloat16* B = Bterm[t];
#pragma unroll
        for (int k = 0; k < 4; k++) {
            int kb = k * 16;
            uint32_t af[2][4];
#pragma unroll
            for (int mi = 0; mi < 2; mi++) {
                int row = wm + mi * 16 + lr;
                af[mi][0] = *(const uint32_t*)(A + row * ASTR + kb + lc);
                af[mi][1] = *(const uint32_t*)(A + (row + 8) * ASTR + kb + lc);
                af[mi][2] = *(const uint32_t*)(A + row * ASTR + kb + 8 + lc);
                af[mi][3] = *(const uint32_t*)(A + (row + 8) * ASTR + kb + 8 + lc);
            }
#pragma unroll
            for (int ni = 0; ni < 8; ni++) {
                int nrow = wn + ni * 8 + lr;
                uint32_t b0 = *(const uint32_t*)(B + nrow * ASTR + kb + lc);
                uint32_t b1 = *(const uint32_t*)(B + nrow * ASTR + kb + 8 + lc);
                mma16816(acc[0][ni], af[0], b0, b1);
                mma16816(acc[1][ni], af[1], b0, b1);
            }
        }
    }

#pragma unroll
    for (int mi = 0; mi < 2; mi++) {
        int crow = c0 + wm + mi * 16 + lr;
        float bv0 = 8192.0f * b3[crow];
        float bv1 = 8192.0f * b3[crow + 8];
#pragma unroll
        for (int ni = 0; ni < 8; ni++) {
            int q = q0 + wn + ni * 8 + lc;
            int f = q >> 1;
            if (f < NF) {
                float2 v0 = make_float2(acc[mi][ni][0], acc[mi][ni][1]);
                float2 v1 = make_float2(acc[mi][ni][2], acc[mi][ni][3]);
                if (f == 0) { v0.x += bv0; v1.x += bv1; }
                d_Ff[(size_t)crow * NF + f] = v0;
                d_Ff[(size_t)(crow + 8) * NF + f] = v1;
            }
        }
    }
}

#define MMA_SMEM (4 * 128 * ASTR * sizeof(__nv_bfloat16))

// ---------------- frequency contraction (f-tiled, coalesced, register-blocked) ----------------
#define CFT 32
#define CIC 4
#define FSTR 33
#define GSTR 33
#define CON_SMEM (256 * GSTR * sizeof(float2))

__global__ __launch_bounds__(512) void contract_kernel() {
    extern __shared__ float2 csm[];
    float2* Xs = csm;
    float2* Fs = csm + CIC * 8 * 32;
    int tid = threadIdx.x;
    int f0 = blockIdx.x * CFT;
    int fi = tid >> 4;
    int s  = tid & 15;
    int bq = s >> 3;
    int oq = s & 7;

    float2 acc[4][4];
#pragma unroll
    for (int a = 0; a < 4; a++)
#pragma unroll
        for (int b = 0; b < 4; b++) acc[a][b] = make_float2(0.f, 0.f);

    for (int ic0 = 0; ic0 < 32; ic0 += CIC) {
        for (int idx = tid; idx < CIC * 8 * 32; idx += 512) {
            int u = idx & 31;
            int r = idx >> 5;
            int ii = r >> 3, b = r & 7;
            int f = f0 + u;
            Xs[idx] = (f < NF) ? d_Xf[(size_t)(b * 32 + ic0 + ii) * NF + f]
                               : make_float2(0.f, 0.f);
        }
        for (int idx = tid; idx < CIC * 32 * 32; idx += 512) {
            int u = idx & 31;
            int r = idx >> 5;
            int ii = r >> 5, o = r & 31;
            int f = f0 + u;
            Fs[r * FSTR + u] = (f < NF) ? d_Ff[(size_t)(o * 32 + ic0 + ii) * NF + f]
                                        : make_float2(0.f, 0.f);
        }
        __syncthreads();
#pragma unroll
        for (int ii = 0; ii < CIC; ii++) {
            float2 xv[4], fv[4];
#pragma unroll
            for (int bb = 0; bb < 4; bb++)
                xv[bb] = Xs[(ii * 8 + bq * 4 + bb) * 32 + fi];
#pragma unroll
            for (int oo = 0; oo < 4; oo++)
                fv[oo] = Fs[(ii * 32 + oq * 4 + oo) * FSTR + fi];
#pragma unroll
            for (int bb = 0; bb < 4; bb++)
#pragma unroll
                for (int oo = 0; oo < 4; oo++) {
                    float2 xvv = xv[bb], fvv = fv[oo];
                    acc[bb][oo].x = fmaf(xvv.x, fvv.x, acc[bb][oo].x);
                    acc[bb][oo].x = fmaf(-xvv.y, fvv.y, acc[bb][oo].x);
                    acc[bb][oo].y = fmaf(xvv.x, fvv.y, acc[bb][oo].y);
                    acc[bb][oo].y = fmaf(xvv.y, fvv.x, acc[bb][oo].y);
                }
        }
        __syncthreads();
    }
    float2* Gs = csm;
#pragma unroll
    for (int bb = 0; bb < 4; bb++)
#pragma unroll
        for (int oo = 0; oo < 4; oo++) {
            int row = (bq * 4 + bb) * 32 + oq * 4 + oo;
            Gs[row * GSTR + fi] = acc[bb][oo];
        }
    __syncthreads();
    for (int idx = tid; idx < 256 * 32; idx += 512) {
        int u = idx & 31, row = idx >> 5;
        int f = f0 + u;
        if (f < NF) d_Gf[(size_t)row * NF + f] = Gs[row * GSTR + u];
    }
}

// ---------------- inverse rfft + bias ----------------
__global__ __launch_bounds__(512) void irfft_kernel(const float* __restrict__ bias,
                                                    float* __restrict__ out) {
    extern __shared__ float2 sm[];
    float2* A = sm;
    float2* Bp = sm + 4096;
    int tid = threadIdx.x;
    int row = blockIdx.x;
    const float2* G = d_Gf + (size_t)row * NF;
    for (int k = tid; k < MH; k += 512) {
        float2 Xk = G[k];
        float2 Xm = G[MH - k];
        float2 E = make_float2(0.5f * (Xk.x + Xm.x), 0.5f * (Xk.y - Xm.y));
        float2 D = make_float2(0.5f * (Xk.x - Xm.x), 0.5f * (Xk.y + Xm.y));
        float2 Wc = d_TW8[k];
        float2 Winv = make_float2(Wc.x, -Wc.y);
        float2 O = cmulf(Winv, D);
        A[k] = make_float2(E.x - O.y, -(E.y + O.x));
    }
    __syncthreads();
    fft4096(A, A, Bp, tid);
    float bo = bias[row & 31];
    float2* orow = (float2*)(out + (size_t)row * TLEN);
    const float inv = 1.0f / (float)MH;
    for (int k = tid; k < MH; k += 512) {
        float2 z = A[k];
        orow[k] = make_float2(fmaf(z.x, inv, bo), fmaf(-z.y, inv, bo));
    }
}

// ---------------- launch ----------------
extern "C" void kernel_launch(void* const* d_in, const int* in_sizes, int n_in,
                              void* d_out, int out_size) {
    const float* x    = (const float*)d_in[0];
    const float* w1   = (const float*)d_in[1];
    const float* b1   = (const float*)d_in[2];
    const float* w2   = (const float*)d_in[3];
    const float* b2   = (const float*)d_in[4];
    const float* w3   = (const float*)d_in[5];
    const float* b3   = (const float*)d_in[6];
    const float* bias = (const float*)d_in[7];
    float* out = (float*)d_out;

    cudaFuncSetAttribute(rfft_x_kernel, cudaFuncAttributeMaxDynamicSharedMemorySize, (int)FFT_SMEM);
    cudaFuncSetAttribute(rfft_h_kernel, cudaFuncAttributeMaxDynamicSharedMemorySize, (int)FFT_SMEM);
    cudaFuncSetAttribute(irfft_kernel, cudaFuncAttributeMaxDynamicSharedMemorySize, (int)FFT_SMEM);
    cudaFuncSetAttribute(gemm_mma_kernel, cudaFuncAttributeMaxDynamicSharedMemorySize, (int)MMA_SMEM);
    cudaFuncSetAttribute(contract_kernel, cudaFuncAttributeMaxDynamicSharedMemorySize, (int)CON_SMEM);

    // Side stream must JOIN the capture via an event recorded on the capture
    // stream (stream 0) BEFORE any work is launched on it.
    cudaStream_t s2;
    cudaEvent_t evFork, evTW, evW3, evX;
    cudaStreamCreateWithFlags(&s2, cudaStreamNonBlocking);
    cudaEventCreateWithFlags(&evFork, cudaEventDisableTiming);
    cudaEventCreateWithFlags(&evTW, cudaEventDisableTiming);
    cudaEventCreateWithFlags(&evW3, cudaEventDisableTiming);
    cudaEventCreateWithFlags(&evX, cudaEventDisableTiming);

    cudaEventRecord(evFork, 0);
    cudaStreamWaitEvent(s2, evFork, 0);

    // s2 chain: twiddles -> w3 prep -> rfft(x)
    init_tw_kernel<<<16, 512, 0, s2>>>();
    cudaEventRecord(evTW, s2);
    prep_w3_kernel<<<NCOL * NHID / 256, 256, 0, s2>>>(w3);
    cudaEventRecord(evW3, s2);
    rfft_x_kernel<<<NB * NCIN, 512, FFT_SMEM, s2>>>(x);
    cudaEventRecord(evX, s2);

    // s0 critical chain
    mlp_kernel<<<TLEN / 128, 128>>>(w1, b1, w2, b2);
    cudaStreamWaitEvent(0, evTW, 0);
    rfft_h_kernel<<<NHID, 512, FFT_SMEM>>>();            // writes d_Bhi/d_Blo directly
    cudaStreamWaitEvent(0, evW3, 0);
    gemm_mma_kernel<<<dim3(QPAD / 128, NCOL / 128), 256, MMA_SMEM>>>(b3);
    cudaStreamWaitEvent(0, evX, 0);
    contract_kernel<<<(NF + CFT - 1) / CFT, 512, CON_SMEM>>>();
    irfft_kernel<<<NB * NCOUT, 512, FFT_SMEM>>>(bias, out);
}